// round 2
// baseline (speedup 1.0000x reference)
#include <cuda_runtime.h>
#include <cstddef>

// Problem constants (fixed by setup_inputs)
constexpr int D      = 64;
constexpr int N      = 128;
constexpr int NSTEPS = 16;
constexpr int NPOW   = 17;   // M^0 .. M^16

// ---------------- device scratch (no allocations allowed) ----------------
__device__ __align__(16) float  g_M[NPOW][D * D];    // powers of M = W^T - I
__device__            double    g_p[NPOW][NPOW];     // x0-coefficients of x_t
__device__            double    g_q[NPOW][NPOW];     // v0-coefficients of x_t
__device__ __align__(16) float  g_A[NPOW][D * D];    // A_t = sum_j p[t][j] M^j
__device__ __align__(16) float  g_B[NPOW][D * D];    // B_t = sum_j q[t][j] M^j
__device__ __align__(16) float  g_R[NSTEPS][D * D];  // [s][i][a] = R_{15-s}[a,i]
__device__ __align__(16) float  g_X[NSTEPS][N * D];  // x_s, s = 0..15

// 64x64x64 matmul helper: C = A*B, operands staged through smem, 256 threads.
__device__ __forceinline__ void mm64(const float* __restrict__ A,
                                     const float* __restrict__ B,
                                     float* __restrict__ C,
                                     float* sA, float* sB, int tid) {
    __syncthreads();
    for (int e = tid; e < D * D; e += 256) { sA[e] = A[e]; sB[e] = B[e]; }
    __syncthreads();
    const int r0 = (tid >> 4) << 2;
    const int c0 = (tid & 15) << 2;
    float acc[4][4] = {};
#pragma unroll 16
    for (int k = 0; k < D; k++) {
        float4 b = *(const float4*)&sB[k * D + c0];
#pragma unroll
        for (int i = 0; i < 4; i++) {
            float a = sA[(r0 + i) * D + k];
            acc[i][0] += a * b.x; acc[i][1] += a * b.y;
            acc[i][2] += a * b.z; acc[i][3] += a * b.w;
        }
    }
    __syncthreads();
#pragma unroll
    for (int i = 0; i < 4; i++) {
        *(float4*)&C[(r0 + i) * D + c0] =
            make_float4(acc[i][0], acc[i][1], acc[i][2], acc[i][3]);
    }
    __syncthreads();
}

// K0: scalar coefficient recurrences (thread 0) + M^0..M^4 (1 block).
__global__ void k0_init(const float* __restrict__ W) {
    __shared__ __align__(16) float sA[D * D];
    __shared__ __align__(16) float sB[D * D];
    const int tid = threadIdx.x;

    if (tid == 0) {
        const double dt = 0.01;
        double p[NPOW] = {}, q[NPOW] = {}, u[NPOW] = {}, w[NPOW] = {};
        p[0] = 1.0; w[0] = 1.0;
        for (int j = 0; j < NPOW; j++) { g_p[0][j] = p[j]; g_q[0][j] = q[j]; }
        for (int t = 0; t < NSTEPS; t++) {
            // v' = v + dt*x*M  (multiplying by M shifts the power index by 1)
            for (int j = NPOW - 1; j >= 1; j--) {
                u[j] += dt * p[j - 1];
                w[j] += dt * q[j - 1];
            }
            // x' = x + dt*v'
            for (int j = 0; j < NPOW; j++) {
                p[j] += dt * u[j];
                q[j] += dt * w[j];
                g_p[t + 1][j] = p[j];
                g_q[t + 1][j] = q[j];
            }
        }
    }
    // M^0 = I ; M^1 = W^T - I (row-vector convention: (x*M)[c] = sum_r x[r]M[r][c])
    for (int e = tid; e < D * D; e += 256) {
        int r = e >> 6, c = e & 63;
        float del = (r == c) ? 1.0f : 0.0f;
        g_M[0][e] = del;
        g_M[1][e] = W[c * D + r] - del;
    }
    mm64(g_M[1], g_M[1], g_M[2], sA, sB, tid);
    mm64(g_M[2], g_M[1], g_M[3], sA, sB, tid);
    mm64(g_M[2], g_M[2], g_M[4], sA, sB, tid);
}

// K1: M^5..M^16 in parallel (12 blocks). Block for power jp = 4d + r does
// C = M^r; repeat d times: C = M^4 * C (1..3 local matmuls).
__global__ void k1_powers() {
    __shared__ __align__(16) float sA[D * D];
    __shared__ __align__(16) float sC[D * D];
    const int tid = threadIdx.x;
    const int jp = 5 + blockIdx.x;     // 5..16
    const int d  = (jp - 1) >> 2;      // 1..3
    const int r  = jp - 4 * d;         // 1..4
    for (int e = tid; e < D * D; e += 256) { sA[e] = g_M[4][e]; sC[e] = g_M[r][e]; }
    __syncthreads();
    const int r0 = (tid >> 4) << 2;
    const int c0 = (tid & 15) << 2;
    for (int it = 0; it < d; it++) {
        float acc[4][4] = {};
#pragma unroll 16
        for (int k = 0; k < D; k++) {
            float4 b = *(const float4*)&sC[k * D + c0];
#pragma unroll
            for (int i = 0; i < 4; i++) {
                float a = sA[(r0 + i) * D + k];
                acc[i][0] += a * b.x; acc[i][1] += a * b.y;
                acc[i][2] += a * b.z; acc[i][3] += a * b.w;
            }
        }
        __syncthreads();
#pragma unroll
        for (int i = 0; i < 4; i++) {
            *(float4*)&sC[(r0 + i) * D + c0] =
                make_float4(acc[i][0], acc[i][1], acc[i][2], acc[i][3]);
        }
        __syncthreads();
    }
    for (int e = tid; e < D * D; e += 256) g_M[jp][e] = sC[e];
}

// K2: polynomial combinations.
//  blocks 0..33 : g_A[t] / g_B[t]  (t = b>>1, A/B = b&1)
//  blocks 34..49: g_R[s][i][a] = sum_j rho_{15-s,j} * M^j[a][i]  (smem transpose)
__global__ void k2_combine() {
    __shared__ float sM[64 * 65];
    const int tid = threadIdx.x, b = blockIdx.x;
    const double dt = 0.01;
    if (b < 34) {
        const int t = b >> 1, isB = b & 1;
        float coef[NPOW];
#pragma unroll
        for (int j = 0; j < NPOW; j++)
            coef[j] = (float)(isB ? g_q[t][j] : g_p[t][j]);
        float* out = isB ? g_B[t] : g_A[t];
        for (int e = tid; e < D * D; e += 256) {
            float acc = 0.0f;
#pragma unroll
            for (int j = 0; j < NPOW; j++) acc += coef[j] * g_M[j][e];
            out[e] = acc;
        }
    } else {
        const int s = b - 34;          // 0..15
        const int k = 15 - s;
        float coef[NPOW];
#pragma unroll
        for (int j = 0; j < NPOW; j++)
            coef[j] = (float)(dt * dt * g_p[k][j] + dt * g_q[k][j]);
        float acc[16] = {};
        for (int j = 0; j < NPOW; j++) {
            __syncthreads();
            for (int e = tid; e < D * D; e += 256)
                sM[(e >> 6) * 65 + (e & 63)] = g_M[j][e];   // sM[row][col], padded
            __syncthreads();
#pragma unroll
            for (int c = 0; c < 16; c++) {
                int e = tid + 256 * c;
                int i = e >> 6, a = e & 63;
                acc[c] += coef[j] * sM[a * 65 + i];          // M^j[a][i]
            }
        }
        for (int c = 0; c < 16; c++) g_R[s][tid + 256 * c] = acc[c];
    }
}

// K3: x_t = x0*A_t + v0*B_t for t=0..16. Writes g_X[t] (t<16) and traj frames.
// 68 blocks = 17 t-values x 4 row-splits, 256 threads.
__global__ void k3_traj(const float* __restrict__ x0, const float* __restrict__ v0,
                        float* __restrict__ out) {
    const int b = blockIdx.x;
    const int t = b >> 2, ns = b & 3;
    const int tid = threadIdx.x;
    const int row = ns * 32 + (tid >> 3);
    const int c0  = (tid & 7) << 3;
    const float* __restrict__ Am = g_A[t];
    const float* __restrict__ Bm = g_B[t];
    const float* __restrict__ xr = x0 + row * D;
    const float* __restrict__ vr = v0 + row * D;
    float acc[8] = {};
#pragma unroll 8
    for (int k = 0; k < D; k++) {
        float xv = xr[k], vv = vr[k];
        float4 a0 = *(const float4*)&Am[k * D + c0];
        float4 a1 = *(const float4*)&Am[k * D + c0 + 4];
        float4 b0 = *(const float4*)&Bm[k * D + c0];
        float4 b1 = *(const float4*)&Bm[k * D + c0 + 4];
        acc[0] += xv * a0.x + vv * b0.x;  acc[1] += xv * a0.y + vv * b0.y;
        acc[2] += xv * a0.z + vv * b0.z;  acc[3] += xv * a0.w + vv * b0.w;
        acc[4] += xv * a1.x + vv * b1.x;  acc[5] += xv * a1.y + vv * b1.y;
        acc[6] += xv * a1.z + vv * b1.z;  acc[7] += xv * a1.w + vv * b1.w;
    }
    float4 lo = make_float4(acc[0], acc[1], acc[2], acc[3]);
    float4 hi = make_float4(acc[4], acc[5], acc[6], acc[7]);
    if (t < NSTEPS) {
        *(float4*)&g_X[t][row * D + c0]     = lo;
        *(float4*)&g_X[t][row * D + c0 + 4] = hi;
    }
    if ((t & 3) == 0) {
        float* o = out + (size_t)(t >> 2) * (N * D) + row * D + c0;
        *(float4*)o       = lo;
        *(float4*)(o + 4) = hi;
    }
}

// K4: jac[n][i][a][b] = sum_s g_R[s][i][a] * g_X[s][n][b].
// Block covers (2 n) x (2 i) x 64a x 64b = 16384 outputs; thread does 8x8 tile.
__global__ void __launch_bounds__(256, 2) k4_jac(float* __restrict__ jac) {
    __shared__ __align__(16) float sR[NSTEPS][2][D];
    __shared__ __align__(16) float sX[NSTEPS][2][D];
    const int tid = threadIdx.x, bid = blockIdx.x;
    const int n0 = (bid >> 5) << 1;   // 0,2,..,126
    const int i0 = (bid & 31) << 1;   // 0,2,..,62
    for (int e = tid; e < NSTEPS * 2 * D; e += 256) {
        int s = e >> 7, il = (e >> 6) & 1, a = e & 63;
        sR[s][il][a] = g_R[s][(i0 + il) * D + a];
        sX[s][il][a] = g_X[s][(n0 + il) * D + a];
    }
    __syncthreads();
    const int nl  = (tid >> 7) & 1;
    const int il  = (tid >> 6) & 1;
    const int idx = tid & 63;
    const int a0  = (idx >> 3) << 3;
    const int b0  = (idx & 7) << 3;
    float acc[8][8] = {};
#pragma unroll
    for (int s = 0; s < NSTEPS; s++) {
        float ra[8], xb[8];
        *(float4*)&ra[0] = *(const float4*)&sR[s][il][a0];
        *(float4*)&ra[4] = *(const float4*)&sR[s][il][a0 + 4];
        *(float4*)&xb[0] = *(const float4*)&sX[s][nl][b0];
        *(float4*)&xb[4] = *(const float4*)&sX[s][nl][b0 + 4];
#pragma unroll
        for (int ia = 0; ia < 8; ia++)
#pragma unroll
            for (int ib = 0; ib < 8; ib++)
                acc[ia][ib] += ra[ia] * xb[ib];
    }
    const size_t base = (((size_t)(n0 + nl) * D + (i0 + il)) * D) * D;
#pragma unroll
    for (int ia = 0; ia < 8; ia++) {
        float* p = jac + base + (size_t)(a0 + ia) * D + b0;
        *(float4*)p       = make_float4(acc[ia][0], acc[ia][1], acc[ia][2], acc[ia][3]);
        *(float4*)(p + 4) = make_float4(acc[ia][4], acc[ia][5], acc[ia][6], acc[ia][7]);
    }
}

extern "C" void kernel_launch(void* const* d_in, const int* in_sizes, int n_in,
                              void* d_out, int out_size) {
    const float* x0 = (const float*)d_in[0];
    const float* v0 = (const float*)d_in[1];
    const float* W  = (const float*)d_in[2];
    float* out = (float*)d_out;
    // output = [traj (frames x N x D)] then [jac (N x D x D x D)]
    float* jac = out + ((size_t)out_size - (size_t)N * D * D * D);

    k0_init<<<1, 256>>>(W);
    k1_powers<<<12, 256>>>();
    k2_combine<<<50, 256>>>();
    k3_traj<<<68, 256>>>(x0, v0, out);
    k4_jac<<<2048, 256>>>(jac);
}

// round 3
// speedup vs baseline: 1.2612x; 1.2612x over previous
#include <cuda_runtime.h>
#include <cstddef>

// Problem constants (fixed by setup_inputs)
constexpr int D      = 64;
constexpr int N      = 128;
constexpr int NSTEPS = 16;
constexpr int NPOW   = 17;   // M^0 .. M^16

// ---------------- device scratch (no allocations allowed) ----------------
__device__ __align__(16) float  g_M[NPOW][D * D];    // powers of M = W^T - I
__device__            double    g_pd[NPOW][NPOW];    // x0-coeffs of x_t (double)
__device__            double    g_qd[NPOW][NPOW];    // v0-coeffs of x_t (double)
__device__            float     g_cA[NPOW][NPOW];    // float copies for k2
__device__            float     g_cB[NPOW][NPOW];
__device__            float     g_cR[NSTEPS][NPOW];  // dt^2*p[15-s] + dt*q[15-s]
__device__ __align__(16) float  g_A[NPOW][D * D];    // A_t = sum_j cA[t][j] M^j
__device__ __align__(16) float  g_B[NPOW][D * D];    // B_t = sum_j cB[t][j] M^j
__device__ __align__(16) float  g_R[NSTEPS][D * D];  // [s][i][a] = R_{15-s}[a,i]
__device__ __align__(16) float  g_X[NSTEPS][N * D];  // x_s, s = 0..15

// 64x64x64 matmul helper: C = A*B, operands staged through smem, 256 threads.
__device__ __forceinline__ void mm64(const float* __restrict__ A,
                                     const float* __restrict__ B,
                                     float* __restrict__ C,
                                     float* sA, float* sB, int tid) {
    __syncthreads();
    for (int e = tid; e < D * D; e += 256) { sA[e] = A[e]; sB[e] = B[e]; }
    __syncthreads();
    const int r0 = (tid >> 4) << 2;
    const int c0 = (tid & 15) << 2;
    float acc[4][4] = {};
#pragma unroll 16
    for (int k = 0; k < D; k++) {
        float4 b = *(const float4*)&sB[k * D + c0];
#pragma unroll
        for (int i = 0; i < 4; i++) {
            float a = sA[(r0 + i) * D + k];
            acc[i][0] += a * b.x; acc[i][1] += a * b.y;
            acc[i][2] += a * b.z; acc[i][3] += a * b.w;
        }
    }
    __syncthreads();
#pragma unroll
    for (int i = 0; i < 4; i++) {
        *(float4*)&C[(r0 + i) * D + c0] =
            make_float4(acc[i][0], acc[i][1], acc[i][2], acc[i][3]);
    }
    __syncthreads();
}

// K0: warp-parallel coefficient recurrences + M^0..M^4 (1 block).
// Lane j of warp 0 owns power index j; the j-1 coupling rides shfl_up.
__global__ void k0_init(const float* __restrict__ W) {
    __shared__ __align__(16) float sA[D * D];
    __shared__ __align__(16) float sB[D * D];
    const int tid = threadIdx.x;

    if (tid < 32) {
        const double dt = 0.01;
        const int j = tid;
        double p = (j == 0) ? 1.0 : 0.0, q = 0.0;
        double u = 0.0, w = (j == 0) ? 1.0 : 0.0;
        if (j < NPOW) {
            g_pd[0][j] = p; g_qd[0][j] = q;
            g_cA[0][j] = (float)p; g_cB[0][j] = (float)q;
        }
        for (int t = 0; t < NSTEPS; t++) {
            double pm1 = __shfl_up_sync(0xffffffffu, p, 1);
            double qm1 = __shfl_up_sync(0xffffffffu, q, 1);
            if (j == 0) { pm1 = 0.0; qm1 = 0.0; }
            u += dt * pm1;          // v' = v + dt*x*M  (power shift by 1)
            w += dt * qm1;
            p += dt * u;            // x' = x + dt*v'
            q += dt * w;
            if (j < NPOW) {
                g_pd[t + 1][j] = p; g_qd[t + 1][j] = q;
                g_cA[t + 1][j] = (float)p; g_cB[t + 1][j] = (float)q;
            }
        }
    }
    __syncthreads();
    for (int e = tid; e < NSTEPS * NPOW; e += 256) {
        const int s = e / NPOW, j = e % NPOW;
        const double dt = 0.01;
        g_cR[s][j] = (float)(dt * dt * g_pd[15 - s][j] + dt * g_qd[15 - s][j]);
    }
    // M^0 = I ; M^1 = W^T - I (row-vector convention: (x*M)[c] = sum_r x[r]M[r][c])
    for (int e = tid; e < D * D; e += 256) {
        int r = e >> 6, c = e & 63;
        float del = (r == c) ? 1.0f : 0.0f;
        g_M[0][e] = del;
        g_M[1][e] = W[c * D + r] - del;
    }
    mm64(g_M[1], g_M[1], g_M[2], sA, sB, tid);
    mm64(g_M[2], g_M[1], g_M[3], sA, sB, tid);
    mm64(g_M[2], g_M[2], g_M[4], sA, sB, tid);
}

// K1: M^5..M^16 in parallel (12 blocks). Block for power jp = 4d + r does
// C = M^r; repeat d times: C = M^4 * C (1..3 local matmuls).
__global__ void k1_powers() {
    __shared__ __align__(16) float sA[D * D];
    __shared__ __align__(16) float sC[D * D];
    const int tid = threadIdx.x;
    const int jp = 5 + blockIdx.x;     // 5..16
    const int d  = (jp - 1) >> 2;      // 1..3
    const int r  = jp - 4 * d;         // 1..4
    for (int e = tid; e < D * D; e += 256) { sA[e] = g_M[4][e]; sC[e] = g_M[r][e]; }
    __syncthreads();
    const int r0 = (tid >> 4) << 2;
    const int c0 = (tid & 15) << 2;
    for (int it = 0; it < d; it++) {
        float acc[4][4] = {};
#pragma unroll 16
        for (int k = 0; k < D; k++) {
            float4 b = *(const float4*)&sC[k * D + c0];
#pragma unroll
            for (int i = 0; i < 4; i++) {
                float a = sA[(r0 + i) * D + k];
                acc[i][0] += a * b.x; acc[i][1] += a * b.y;
                acc[i][2] += a * b.z; acc[i][3] += a * b.w;
            }
        }
        __syncthreads();
#pragma unroll
        for (int i = 0; i < 4; i++) {
            *(float4*)&sC[(r0 + i) * D + c0] =
                make_float4(acc[i][0], acc[i][1], acc[i][2], acc[i][3]);
        }
        __syncthreads();
    }
    for (int e = tid; e < D * D; e += 256) g_M[jp][e] = sC[e];
}

// K2: polynomial combinations.
//  blocks 0..33 : g_A[t] / g_B[t]  (t = b>>1, A/B = b&1)
//  blocks 34..49: g_R[s][i][a] = sum_j cR[s][j] * M^j[a][i]  (smem transpose)
__global__ void k2_combine() {
    __shared__ float sM[64 * 65];
    const int tid = threadIdx.x, b = blockIdx.x;
    if (b < 34) {
        const int t = b >> 1, isB = b & 1;
        float coef[NPOW];
#pragma unroll
        for (int j = 0; j < NPOW; j++)
            coef[j] = isB ? g_cB[t][j] : g_cA[t][j];
        float* out = isB ? g_B[t] : g_A[t];
        for (int e = tid; e < D * D; e += 256) {
            float acc = 0.0f;
#pragma unroll
            for (int j = 0; j < NPOW; j++) acc += coef[j] * g_M[j][e];
            out[e] = acc;
        }
    } else {
        const int s = b - 34;          // 0..15
        float coef[NPOW];
#pragma unroll
        for (int j = 0; j < NPOW; j++) coef[j] = g_cR[s][j];
        float acc[16] = {};
        for (int j = 0; j < NPOW; j++) {
            __syncthreads();
            for (int e = tid; e < D * D; e += 256)
                sM[(e >> 6) * 65 + (e & 63)] = g_M[j][e];   // sM[row][col], padded
            __syncthreads();
#pragma unroll
            for (int c = 0; c < 16; c++) {
                int e = tid + 256 * c;
                int i = e >> 6, a = e & 63;
                acc[c] += coef[j] * sM[a * 65 + i];          // M^j[a][i]
            }
        }
        for (int c = 0; c < 16; c++) g_R[s][tid + 256 * c] = acc[c];
    }
}

// K3: x_t = x0*A_t + v0*B_t for t=0..16, with A_t/B_t staged in SMEM.
// 68 blocks = 17 t-values x 4 row-groups of 32 rows, 256 threads.
__global__ void k3_traj(const float* __restrict__ x0, const float* __restrict__ v0,
                        float* __restrict__ out) {
    __shared__ __align__(16) float sA[D * D];   // 16 KB
    __shared__ __align__(16) float sB[D * D];   // 16 KB
    const int b   = blockIdx.x;
    const int t   = b >> 2, ns = b & 3;
    const int tid = threadIdx.x;
    {
        const float* __restrict__ Ag = g_A[t];
        const float* __restrict__ Bg = g_B[t];
        for (int e = tid * 4; e < D * D; e += 256 * 4) {
            *(float4*)&sA[e] = *(const float4*)&Ag[e];
            *(float4*)&sB[e] = *(const float4*)&Bg[e];
        }
    }
    __syncthreads();
    const int row = ns * 32 + (tid >> 3);
    const int c0  = (tid & 7) << 3;
    const float* __restrict__ xr = x0 + row * D;
    const float* __restrict__ vr = v0 + row * D;
    float acc[8] = {};
#pragma unroll 8
    for (int k = 0; k < D; k++) {
        float xv = __ldg(&xr[k]), vv = __ldg(&vr[k]);
        float4 a0 = *(const float4*)&sA[k * D + c0];
        float4 a1 = *(const float4*)&sA[k * D + c0 + 4];
        float4 b0 = *(const float4*)&sB[k * D + c0];
        float4 b1 = *(const float4*)&sB[k * D + c0 + 4];
        acc[0] += xv * a0.x + vv * b0.x;  acc[1] += xv * a0.y + vv * b0.y;
        acc[2] += xv * a0.z + vv * b0.z;  acc[3] += xv * a0.w + vv * b0.w;
        acc[4] += xv * a1.x + vv * b1.x;  acc[5] += xv * a1.y + vv * b1.y;
        acc[6] += xv * a1.z + vv * b1.z;  acc[7] += xv * a1.w + vv * b1.w;
    }
    float4 lo = make_float4(acc[0], acc[1], acc[2], acc[3]);
    float4 hi = make_float4(acc[4], acc[5], acc[6], acc[7]);
    if (t < NSTEPS) {
        *(float4*)&g_X[t][row * D + c0]     = lo;
        *(float4*)&g_X[t][row * D + c0 + 4] = hi;
    }
    if ((t & 3) == 0) {
        float* o = out + (size_t)(t >> 2) * (N * D) + row * D + c0;
        *(float4*)o       = lo;
        *(float4*)(o + 4) = hi;
    }
}

// K4: jac[n][i][a][b] = sum_s g_R[s][i][a] * g_X[s][n][b].
// Block covers (2 n) x (2 i) x 64a x 64b = 16384 outputs; thread does 8x8 tile.
__global__ void __launch_bounds__(256, 2) k4_jac(float* __restrict__ jac) {
    __shared__ __align__(16) float sR[NSTEPS][2][D];
    __shared__ __align__(16) float sX[NSTEPS][2][D];
    const int tid = threadIdx.x, bid = blockIdx.x;
    const int n0 = (bid >> 5) << 1;   // 0,2,..,126
    const int i0 = (bid & 31) << 1;   // 0,2,..,62
    for (int e = tid; e < NSTEPS * 2 * D; e += 256) {
        int s = e >> 7, il = (e >> 6) & 1, a = e & 63;
        sR[s][il][a] = g_R[s][(i0 + il) * D + a];
        sX[s][il][a] = g_X[s][(n0 + il) * D + a];
    }
    __syncthreads();
    const int nl  = (tid >> 7) & 1;
    const int il  = (tid >> 6) & 1;
    const int idx = tid & 63;
    const int a0  = (idx >> 3) << 3;
    const int b0  = (idx & 7) << 3;
    float acc[8][8] = {};
#pragma unroll
    for (int s = 0; s < NSTEPS; s++) {
        float ra[8], xb[8];
        *(float4*)&ra[0] = *(const float4*)&sR[s][il][a0];
        *(float4*)&ra[4] = *(const float4*)&sR[s][il][a0 + 4];
        *(float4*)&xb[0] = *(const float4*)&sX[s][nl][b0];
        *(float4*)&xb[4] = *(const float4*)&sX[s][nl][b0 + 4];
#pragma unroll
        for (int ia = 0; ia < 8; ia++)
#pragma unroll
            for (int ib = 0; ib < 8; ib++)
                acc[ia][ib] += ra[ia] * xb[ib];
    }
    const size_t base = (((size_t)(n0 + nl) * D + (i0 + il)) * D) * D;
#pragma unroll
    for (int ia = 0; ia < 8; ia++) {
        float* p = jac + base + (size_t)(a0 + ia) * D + b0;
        *(float4*)p       = make_float4(acc[ia][0], acc[ia][1], acc[ia][2], acc[ia][3]);
        *(float4*)(p + 4) = make_float4(acc[ia][4], acc[ia][5], acc[ia][6], acc[ia][7]);
    }
}

extern "C" void kernel_launch(void* const* d_in, const int* in_sizes, int n_in,
                              void* d_out, int out_size) {
    const float* x0 = (const float*)d_in[0];
    const float* v0 = (const float*)d_in[1];
    const float* W  = (const float*)d_in[2];
    float* out = (float*)d_out;
    // output = [traj (frames x N x D)] then [jac (N x D x D x D)]
    float* jac = out + ((size_t)out_size - (size_t)N * D * D * D);

    k0_init<<<1, 256>>>(W);
    k1_powers<<<12, 256>>>();
    k2_combine<<<50, 256>>>();
    k3_traj<<<68, 256>>>(x0, v0, out);
    k4_jac<<<2048, 256>>>(jac);
}

// round 4
// speedup vs baseline: 2.2189x; 1.7594x over previous
#include <cuda_runtime.h>
#include <cstddef>

// Problem constants (fixed by setup_inputs)
constexpr int D      = 64;
constexpr int N      = 128;
constexpr int NSTEPS = 16;

// ---------------- device scratch (no allocations allowed) ----------------
__device__ __align__(16) float g_R[NSTEPS][D * D];  // [s][i*64+a] = R_{15-s}[a][i]
__device__ __align__(16) float g_X[NSTEPS][N * D];  // x_s, s = 0..15

// KPREP: direct row-wise simulation of BOTH systems in one launch.
//   rows 0..127   : state rows (x0, v0)            -> g_X[t], traj frames
//   rows 128..191 : propagator rows a = row-128,
//                   X0 = dt^2*e_a, V0 = dt*e_a     -> X_k = R_k, stored transposed
// One warp per row; lane owns 2 columns; M columns live in registers.
// M[k][c] = W[c][k] - delta(k,c)  (row-vector convention: f = x*M).
__global__ void __launch_bounds__(128) kprep(const float* __restrict__ x0,
                                             const float* __restrict__ v0,
                                             const float* __restrict__ W,
                                             float* __restrict__ out) {
    __shared__ float sX[4][D];
    const int tid = threadIdx.x;
    const int w   = tid >> 5;                  // warp = local row
    const int l   = tid & 31;
    const int row = blockIdx.x * 4 + w;        // 0..191
    const int c0  = 2 * l;
    const float dt = 0.01f;
    const bool is_state = (row < N);
    const int a = row - N;                     // propagator row index (if !is_state)

    // Load this lane's two M columns into registers (fully unrolled).
    float mA[D], mB[D];
    {
        const float4* wa = (const float4*)(W + (size_t)c0 * D);
        const float4* wb = (const float4*)(W + (size_t)(c0 + 1) * D);
#pragma unroll
        for (int q = 0; q < 16; q++) {
            float4 va = wa[q], vb = wb[q];
            const int k = 4 * q;
            mA[k+0] = va.x - ((k+0) == c0     ? 1.0f : 0.0f);
            mA[k+1] = va.y - ((k+1) == c0     ? 1.0f : 0.0f);
            mA[k+2] = va.z - ((k+2) == c0     ? 1.0f : 0.0f);
            mA[k+3] = va.w - ((k+3) == c0     ? 1.0f : 0.0f);
            mB[k+0] = vb.x - ((k+0) == c0 + 1 ? 1.0f : 0.0f);
            mB[k+1] = vb.y - ((k+1) == c0 + 1 ? 1.0f : 0.0f);
            mB[k+2] = vb.z - ((k+2) == c0 + 1 ? 1.0f : 0.0f);
            mB[k+3] = vb.w - ((k+3) == c0 + 1 ? 1.0f : 0.0f);
        }
    }

    // Initial state for this lane's two columns.
    float2 xl, vl;
    if (is_state) {
        xl = *(const float2*)(x0 + (size_t)row * D + c0);
        vl = *(const float2*)(v0 + (size_t)row * D + c0);
    } else {
        xl = make_float2(c0 == a ? dt * dt : 0.0f, (c0 + 1) == a ? dt * dt : 0.0f);
        vl = make_float2(c0 == a ? dt      : 0.0f, (c0 + 1) == a ? dt      : 0.0f);
    }

    // t = 0 outputs.
    if (is_state) {
        *(float2*)&g_X[0][row * D + c0] = xl;                 // x_0
        *(float2*)(out + (size_t)row * D + c0) = xl;          // traj frame 0
    } else {
        g_R[15][c0 * D + a]       = xl.x;                     // R_0 transposed
        g_R[15][(c0 + 1) * D + a] = xl.y;
    }

    *(float2*)&sX[w][c0] = xl;
    __syncwarp();

#pragma unroll 1
    for (int t = 1; t <= NSTEPS; t++) {
        float2 y = make_float2(0.0f, 0.0f);
#pragma unroll
        for (int k = 0; k < D; k++) {
            float xk = sX[w][k];
            y.x += xk * mA[k];
            y.y += xk * mB[k];
        }
        vl.x += dt * y.x;  vl.y += dt * y.y;
        xl.x += dt * vl.x; xl.y += dt * vl.y;
        __syncwarp();
        *(float2*)&sX[w][c0] = xl;
        __syncwarp();

        if (is_state) {
            if (t < NSTEPS)
                *(float2*)&g_X[t][row * D + c0] = xl;
            if ((t & 3) == 0) {
                float* o = out + (size_t)(t >> 2) * (N * D) + (size_t)row * D + c0;
                *(float2*)o = xl;
            }
        } else if (t < NSTEPS) {
            g_R[15 - t][c0 * D + a]       = xl.x;
            g_R[15 - t][(c0 + 1) * D + a] = xl.y;
        }
    }
}

// K4: jac[n][i][a][b] = sum_s g_R[s][i][a] * g_X[s][n][b].
// Block covers (2 n) x (2 i) x 64a x 64b = 16384 outputs; thread does 8x8 tile.
__global__ void __launch_bounds__(256, 2) k4_jac(float* __restrict__ jac) {
    __shared__ __align__(16) float sR[NSTEPS][2][D];
    __shared__ __align__(16) float sX[NSTEPS][2][D];
    const int tid = threadIdx.x, bid = blockIdx.x;
    const int n0 = (bid >> 5) << 1;   // 0,2,..,126
    const int i0 = (bid & 31) << 1;   // 0,2,..,62
    for (int e = tid; e < NSTEPS * 2 * D; e += 256) {
        int s = e >> 7, il = (e >> 6) & 1, aa = e & 63;
        sR[s][il][aa] = g_R[s][(i0 + il) * D + aa];
        sX[s][il][aa] = g_X[s][(n0 + il) * D + aa];
    }
    __syncthreads();
    const int nl  = (tid >> 7) & 1;
    const int il  = (tid >> 6) & 1;
    const int idx = tid & 63;
    const int a0  = (idx >> 3) << 3;
    const int b0  = (idx & 7) << 3;
    float acc[8][8] = {};
#pragma unroll
    for (int s = 0; s < NSTEPS; s++) {
        float ra[8], xb[8];
        *(float4*)&ra[0] = *(const float4*)&sR[s][il][a0];
        *(float4*)&ra[4] = *(const float4*)&sR[s][il][a0 + 4];
        *(float4*)&xb[0] = *(const float4*)&sX[s][nl][b0];
        *(float4*)&xb[4] = *(const float4*)&sX[s][nl][b0 + 4];
#pragma unroll
        for (int ia = 0; ia < 8; ia++)
#pragma unroll
            for (int ib = 0; ib < 8; ib++)
                acc[ia][ib] += ra[ia] * xb[ib];
    }
    const size_t base = (((size_t)(n0 + nl) * D + (i0 + il)) * D) * D;
#pragma unroll
    for (int ia = 0; ia < 8; ia++) {
        float* p = jac + base + (size_t)(a0 + ia) * D + b0;
        *(float4*)p       = make_float4(acc[ia][0], acc[ia][1], acc[ia][2], acc[ia][3]);
        *(float4*)(p + 4) = make_float4(acc[ia][4], acc[ia][5], acc[ia][6], acc[ia][7]);
    }
}

extern "C" void kernel_launch(void* const* d_in, const int* in_sizes, int n_in,
                              void* d_out, int out_size) {
    const float* x0 = (const float*)d_in[0];
    const float* v0 = (const float*)d_in[1];
    const float* W  = (const float*)d_in[2];
    float* out = (float*)d_out;
    // output = [traj (frames x N x D)] then [jac (N x D x D x D)]
    float* jac = out + ((size_t)out_size - (size_t)N * D * D * D);

    kprep<<<48, 128>>>(x0, v0, W, out);
    k4_jac<<<2048, 256>>>(jac);
}

// round 5
// speedup vs baseline: 2.9150x; 1.3137x over previous
#include <cuda_runtime.h>
#include <cstddef>

// Problem constants (fixed by setup_inputs)
constexpr int D      = 64;
constexpr int N      = 128;
constexpr int NSTEPS = 16;

// ---------------- device scratch (no allocations allowed) ----------------
__device__ __align__(16) float g_R[NSTEPS][D * D];  // [s][i*64+a] = R_{15-s}[a][i]
__device__ __align__(16) float g_X[NSTEPS][N * D];  // x_s, s = 0..15

// KPREP: direct row-wise simulation of BOTH systems in one launch.
//   rows 0..127   : state rows (x0, v0)            -> g_X[t], traj frames
//   rows 128..191 : propagator rows a = row-128,
//                   X0 = dt^2*e_a, V0 = dt*e_a     -> X_k = R_k, stored transposed
// One warp per row; lane owns 2 columns; M columns live in registers.
// M[k][c] = W[c][k] - delta(k,c)  (row-vector convention: f = x*M).
__global__ void __launch_bounds__(128) kprep(const float* __restrict__ x0,
                                             const float* __restrict__ v0,
                                             const float* __restrict__ W,
                                             float* __restrict__ out) {
    __shared__ float sX[4][D];
    const int tid = threadIdx.x;
    const int w   = tid >> 5;                  // warp = local row
    const int l   = tid & 31;
    const int row = blockIdx.x * 4 + w;        // 0..191
    const int c0  = 2 * l;
    const float dt = 0.01f;
    const bool is_state = (row < N);
    const int a = row - N;                     // propagator row index (if !is_state)

    // Load this lane's two M columns into registers (fully unrolled).
    float mA[D], mB[D];
    {
        const float4* wa = (const float4*)(W + (size_t)c0 * D);
        const float4* wb = (const float4*)(W + (size_t)(c0 + 1) * D);
#pragma unroll
        for (int q = 0; q < 16; q++) {
            float4 va = wa[q], vb = wb[q];
            const int k = 4 * q;
            mA[k+0] = va.x - ((k+0) == c0     ? 1.0f : 0.0f);
            mA[k+1] = va.y - ((k+1) == c0     ? 1.0f : 0.0f);
            mA[k+2] = va.z - ((k+2) == c0     ? 1.0f : 0.0f);
            mA[k+3] = va.w - ((k+3) == c0     ? 1.0f : 0.0f);
            mB[k+0] = vb.x - ((k+0) == c0 + 1 ? 1.0f : 0.0f);
            mB[k+1] = vb.y - ((k+1) == c0 + 1 ? 1.0f : 0.0f);
            mB[k+2] = vb.z - ((k+2) == c0 + 1 ? 1.0f : 0.0f);
            mB[k+3] = vb.w - ((k+3) == c0 + 1 ? 1.0f : 0.0f);
        }
    }

    // Initial state for this lane's two columns.
    float2 xl, vl;
    if (is_state) {
        xl = *(const float2*)(x0 + (size_t)row * D + c0);
        vl = *(const float2*)(v0 + (size_t)row * D + c0);
    } else {
        xl = make_float2(c0 == a ? dt * dt : 0.0f, (c0 + 1) == a ? dt * dt : 0.0f);
        vl = make_float2(c0 == a ? dt      : 0.0f, (c0 + 1) == a ? dt      : 0.0f);
    }

    // t = 0 outputs.
    if (is_state) {
        *(float2*)&g_X[0][row * D + c0] = xl;                 // x_0
        *(float2*)(out + (size_t)row * D + c0) = xl;          // traj frame 0
    } else {
        g_R[15][c0 * D + a]       = xl.x;                     // R_0 transposed
        g_R[15][(c0 + 1) * D + a] = xl.y;
    }

    *(float2*)&sX[w][c0] = xl;
    __syncwarp();

#pragma unroll 1
    for (int t = 1; t <= NSTEPS; t++) {
        float2 y = make_float2(0.0f, 0.0f);
#pragma unroll
        for (int k = 0; k < D; k++) {
            float xk = sX[w][k];
            y.x += xk * mA[k];
            y.y += xk * mB[k];
        }
        vl.x += dt * y.x;  vl.y += dt * y.y;
        xl.x += dt * vl.x; xl.y += dt * vl.y;
        __syncwarp();
        *(float2*)&sX[w][c0] = xl;
        __syncwarp();

        if (is_state) {
            if (t < NSTEPS)
                *(float2*)&g_X[t][row * D + c0] = xl;
            if ((t & 3) == 0) {
                float* o = out + (size_t)(t >> 2) * (N * D) + (size_t)row * D + c0;
                *(float2*)o = xl;
            }
        } else if (t < NSTEPS) {
            g_R[15 - t][c0 * D + a]       = xl.x;
            g_R[15 - t][(c0 + 1) * D + a] = xl.y;
        }
    }
}

// K4: jac[n][i][a][b] = sum_s g_R[s][i][a] * g_X[s][n][b].
// Block covers (2 n) x (2 i) x 64a x 64b = 16384 outputs; thread does an 8x8
// tile using packed fma.rn.f32x2 (FFMA2): accumulators pair along b.
__global__ void __launch_bounds__(256, 2) k4_jac(float* __restrict__ jac) {
    __shared__ __align__(16) float sR[NSTEPS][2][D];
    __shared__ __align__(16) float sX[NSTEPS][2][D];
    const int tid = threadIdx.x, bid = blockIdx.x;
    const int n0 = (bid >> 5) << 1;   // 0,2,..,126
    const int i0 = (bid & 31) << 1;   // 0,2,..,62

    // Vectorized smem fill: sR/sX are [s][il][aa] flat = 512 float4 each.
    {
        float4* sRv = (float4*)sR;
        float4* sXv = (float4*)sX;
#pragma unroll
        for (int v = tid; v < 512; v += 256) {
            const int s  = v >> 5;
            const int il = (v >> 4) & 1;
            const int aa = (v & 15) << 2;
            sRv[v] = *(const float4*)&g_R[s][(i0 + il) * D + aa];
            sXv[v] = *(const float4*)&g_X[s][(n0 + il) * D + aa];
        }
    }
    __syncthreads();

    const int nl  = (tid >> 7) & 1;
    const int il  = (tid >> 6) & 1;
    const int idx = tid & 63;
    const int a0  = (idx >> 3) << 3;
    const int b0  = (idx & 7) << 3;

    unsigned long long acc[8][4];
#pragma unroll
    for (int ia = 0; ia < 8; ia++)
#pragma unroll
        for (int jb = 0; jb < 4; jb++) acc[ia][jb] = 0ull;

#pragma unroll
    for (int s = 0; s < NSTEPS; s++) {
        // xb: 8 floats = 4 packed f32x2 (b is the packed lane pair)
        const ulonglong2 x01 = *(const ulonglong2*)&sX[s][nl][b0];
        const ulonglong2 x23 = *(const ulonglong2*)&sX[s][nl][b0 + 4];
        unsigned long long xb[4] = {x01.x, x01.y, x23.x, x23.y};
        // ra: 8 scalars, each broadcast into both halves of a b64 reg
        const float4 r0 = *(const float4*)&sR[s][il][a0];
        const float4 r1 = *(const float4*)&sR[s][il][a0 + 4];
        const float raf[8] = {r0.x, r0.y, r0.z, r0.w, r1.x, r1.y, r1.z, r1.w};
        unsigned long long rr[8];
#pragma unroll
        for (int ia = 0; ia < 8; ia++) {
            const unsigned int u = __float_as_uint(raf[ia]);
            asm("mov.b64 %0, {%1, %1};" : "=l"(rr[ia]) : "r"(u));
        }
#pragma unroll
        for (int ia = 0; ia < 8; ia++)
#pragma unroll
            for (int jb = 0; jb < 4; jb++)
                asm("fma.rn.f32x2 %0, %1, %2, %0;"
                    : "+l"(acc[ia][jb]) : "l"(rr[ia]), "l"(xb[jb]));
    }

    const size_t base = (((size_t)(n0 + nl) * D + (i0 + il)) * D) * D;
#pragma unroll
    for (int ia = 0; ia < 8; ia++) {
        float* p = jac + base + (size_t)(a0 + ia) * D + b0;
        *(ulonglong2*)p       = make_ulonglong2(acc[ia][0], acc[ia][1]);
        *(ulonglong2*)(p + 4) = make_ulonglong2(acc[ia][2], acc[ia][3]);
    }
}

extern "C" void kernel_launch(void* const* d_in, const int* in_sizes, int n_in,
                              void* d_out, int out_size) {
    const float* x0 = (const float*)d_in[0];
    const float* v0 = (const float*)d_in[1];
    const float* W  = (const float*)d_in[2];
    float* out = (float*)d_out;
    // output = [traj (frames x N x D)] then [jac (N x D x D x D)]
    float* jac = out + ((size_t)out_size - (size_t)N * D * D * D);

    kprep<<<48, 128>>>(x0, v0, W, out);
    k4_jac<<<2048, 256>>>(jac);
}